// round 10
// baseline (speedup 1.0000x reference)
#include <cuda_runtime.h>
#include <math.h>
#include <stdint.h>

#define BB 8
#define HH 8
#define PP 4
#define FEAT 64
#define EMB 32
#define HIN 96
#define GH 32
#define TT 101770

#define TPB 128
#define NT 128
#define AW_STR 100                      // padded stride for staged att_W rows
#define AWBUF (NT * AW_STR)             // 12800 floats per attW buffer
#define HMBUF (GH * 32)                 // 1024 floats per hmid slice

// ---------- persistent scratch ----------
__device__ float g_h1    [BB * 128];
__device__ float g_feats [BB * FEAT];
__device__ float g_featsT[FEAT * BB];   // [k][b]
__device__ float g_embT  [EMB * PP];    // [k][p]
__device__ float g_hmidT [HH * GH * 32];// [h][j][pb]
__device__ float g_gate  [HH * BB];     // [h][b]

// ---------- packed f32x2 helpers ----------
__device__ __forceinline__ unsigned long long pk2(float lo, float hi) {
    unsigned long long r;
    asm("mov.b64 %0, {%1, %2};" : "=l"(r) : "f"(lo), "f"(hi));
    return r;
}
__device__ __forceinline__ unsigned long long fma2(unsigned long long a,
                                                   unsigned long long b,
                                                   unsigned long long c) {
    unsigned long long d;
    asm("fma.rn.f32x2 %0, %1, %2, %3;" : "=l"(d) : "l"(a), "l"(b), "l"(c));
    return d;
}
__device__ __forceinline__ void upk2(unsigned long long v, float& lo, float& hi) {
    asm("mov.b64 {%0, %1}, %2;" : "=f"(lo), "=f"(hi) : "l"(v));
}

// ---------- cp.async helpers ----------
__device__ __forceinline__ void cp16(uint32_t dst_smem, const void* src) {
    asm volatile("cp.async.cg.shared.global [%0], [%1], 16;" :: "r"(dst_smem), "l"(src));
}
__device__ __forceinline__ void cp_commit() { asm volatile("cp.async.commit_group;"); }
template<int N>
__device__ __forceinline__ void cp_wait() {
    asm volatile("cp.async.wait_group %0;" :: "n"(N));
}

// ---------- prep 1a: layer 1, one warp per output (128 blocks x 256 thr) ----------
__global__ void __launch_bounds__(256, 1)
prep1a_kernel(const float* __restrict__ x,
              const float* __restrict__ feW1, const float* __restrict__ feb1)
{
    int g = blockIdx.x * 8 + (threadIdx.x >> 5);
    int lane = threadIdx.x & 31;
    int b = g >> 7, j = g & 127;
    const float* xr = x + b * 784;
    const float* wr = feW1 + j * 784;
    float s = 0.f;
    #pragma unroll 4
    for (int i = lane; i < 784; i += 32) s = fmaf(xr[i], wr[i], s);
    #pragma unroll
    for (int o = 16; o; o >>= 1) s += __shfl_down_sync(0xFFFFFFFFu, s, o);
    if (lane == 0) g_h1[b * 128 + j] = fmaxf(s + feb1[j], 0.f);
}

// ---------- prep fuse: layer 2 (redundant per block) + gate + hmid + embT ----------
__global__ void __launch_bounds__(256, 1)
prep_fuse_kernel(const float* __restrict__ feW2, const float* __restrict__ feb2,
                 const float* __restrict__ gateW, const float* __restrict__ gateb,
                 const float* __restrict__ embeds,
                 const float* __restrict__ genW1, const float* __restrict__ genb1)
{
    int h = blockIdx.x;
    int tid = threadIdx.x;
    __shared__ float s_h1[BB * 128];
    __shared__ float s_feats[BB * FEAT];
    __shared__ float s_emb[PP * EMB];

    for (int i = tid; i < BB * 128; i += 256) s_h1[i] = g_h1[i];
    for (int i = tid; i < PP * EMB; i += 256) s_emb[i] = embeds[i];
    __syncthreads();

    for (int o = tid; o < BB * FEAT; o += 256) {
        int b = o >> 6, f = o & 63;
        float s = feb2[f];
        const float* hr = s_h1 + b * 128;
        const float* wr = feW2 + f * 128;
        #pragma unroll 8
        for (int j = 0; j < 128; j++) s = fmaf(hr[j], wr[j], s);
        s_feats[b * FEAT + f] = s;
        if (h == 0) {
            g_feats[b * FEAT + f] = s;
            g_featsT[f * BB + b] = s;
        }
    }
    __syncthreads();

    if (h == 0 && tid < 8) {
        int r = tid;
        float lg[8];
        float mx = -1e30f;
        #pragma unroll
        for (int c = 0; c < 8; c++) {
            float s = gateb[c];
            const float* fr = s_feats + r * FEAT;
            const float* wr = gateW + c * FEAT;
            #pragma unroll 8
            for (int k = 0; k < FEAT; k++) s = fmaf(fr[k], wr[k], s);
            lg[c] = s;
            mx = fmaxf(mx, s);
        }
        float den = 0.f;
        #pragma unroll
        for (int c = 0; c < 8; c++) { lg[c] = __expf(lg[c] - mx); den += lg[c]; }
        float inv = 1.f / den;
        #pragma unroll
        for (int c = 0; c < 8; c++) g_gate[r * 8 + c] = lg[c] * inv;
    }
    if (h == 0) {
        for (int i = tid; i < EMB * PP; i += 256) {
            int k = i >> 2, p = i & 3;
            g_embT[k * 4 + p] = embeds[p * EMB + k];
        }
    }

    // hmid for head h: layout [j][pb]
    for (int idx = tid; idx < GH * 32; idx += 256) {
        int j = idx >> 5;
        int pb = idx & 31;
        int p = pb >> 3, b = pb & 7;
        const float* w = genW1 + (size_t)(h * GH + j) * HIN;
        float s = genb1[h * GH + j];
        const float* fr = s_feats + b * FEAT;
        #pragma unroll 8
        for (int i = 0; i < FEAT; i++) s = fmaf(fr[i], w[i], s);
        const float* er = s_emb + p * EMB;
        #pragma unroll 8
        for (int i = 0; i < EMB; i++) s = fmaf(er[i], w[FEAT + i], s);
        g_hmidT[(h * GH + j) * 32 + pb] = fmaxf(s, 0.f);
    }
}

// ---------- main kernel: 2 blocks/SM, cp.async double-buffered attW+hmid,
//            genW2 register-prefetched, all broadcast reads as LDS.128 ----------
__global__ void __launch_bounds__(TPB, 2)
main_kernel(const float* __restrict__ genW2, const float* __restrict__ genb2,
            const float* __restrict__ attW,  const float* __restrict__ attb,
            float* __restrict__ out)
{
    extern __shared__ float sm[];
    float* sh_attw   = sm;                          // 2 * 12800
    float* sh_hmid   = sm + 2 * AWBUF;              // 2 * 1024
    float* sh_featsT = sh_hmid + 2 * HMBUF;         // 512
    float* sh_embT   = sh_featsT + FEAT * BB;       // 128
    float* sh_gate   = sh_embT + EMB * PP;          // 64

    int tid = threadIdx.x;
    int t_base = blockIdx.x * NT;
    int t = t_base + tid;
    int tc = (t < TT) ? t : (TT - 1);

    uint32_t smem_u32 = (uint32_t)__cvta_generic_to_shared(sm);

    auto issue_head = [&](int h, int buf) {
        uint32_t base = smem_u32 + (uint32_t)buf * (AWBUF * 4);
        const float* src = attW + (size_t)h * TT * HIN;
        #pragma unroll
        for (int i = 0; i < 24; i++) {
            int v = tid + i * TPB;              // [0, 3072)
            int row = v / 24, c4 = v % 24;
            int tr = t_base + row; if (tr >= TT) tr = TT - 1;
            cp16(base + (uint32_t)(row * AW_STR + c4 * 4) * 4,
                 src + (size_t)tr * HIN + c4 * 4);
        }
        uint32_t hb = smem_u32 + (uint32_t)(2 * AWBUF + buf * HMBUF) * 4;
        const float* hsrc = g_hmidT + (size_t)h * HMBUF;
        #pragma unroll
        for (int i = 0; i < 2; i++) {
            int v = tid + i * TPB;              // [0, 256) float4s
            cp16(hb + (uint32_t)v * 16, hsrc + v * 4);
        }
    };

    issue_head(0, 0);
    cp_commit();

    float abv[8], b2vv[8];
    #pragma unroll
    for (int h = 0; h < HH; h++) {
        abv[h]  = __ldg(attb  + (size_t)h * TT + tc);
        b2vv[h] = __ldg(genb2 + (size_t)h * TT + tc);
    }

    float4 gw[8];
    {
        const float4* gsrc = reinterpret_cast<const float4*>(genW2 + (size_t)tc * GH);
        #pragma unroll
        for (int i = 0; i < 8; i++) gw[i] = __ldg(gsrc + i);
    }

    for (int i = tid; i < FEAT * BB; i += TPB) sh_featsT[i] = g_featsT[i];
    if (tid < EMB * PP) sh_embT[tid] = g_embT[tid];
    if (tid < HH * BB)  sh_gate[tid] = g_gate[tid];

    float acc[32];
    #pragma unroll
    for (int i = 0; i < 32; i++) acc[i] = 0.f;

    const ulonglong2* fts = reinterpret_cast<const ulonglong2*>(sh_featsT);
    const ulonglong2* emt = reinterpret_cast<const ulonglong2*>(sh_embT);

    for (int h = 0; h < HH; h++) {
        if (h < HH - 1) {
            issue_head(h + 1, (h + 1) & 1);
            cp_commit();
            cp_wait<1>();
        } else {
            cp_wait<0>();
        }
        __syncthreads();

        const float* myw   = sh_attw + (h & 1) * AWBUF + tid * AW_STR;
        const float* hmidb = sh_hmid + (h & 1) * HMBUF;

        // ---- W part first: consumes prefetched gw registers; LDS.128 rows ----
        unsigned long long W2r[16];
        #pragma unroll
        for (int q = 0; q < 16; q++) W2r[q] = 0ull;
        #pragma unroll
        for (int j0 = 0; j0 < 8; j0++) {
            float gv[4] = {gw[j0].x, gw[j0].y, gw[j0].z, gw[j0].w};
            #pragma unroll
            for (int jj = 0; jj < 4; jj++) {
                unsigned long long gp = pk2(gv[jj], gv[jj]);
                const ulonglong2* mrow = reinterpret_cast<const ulonglong2*>(
                    hmidb + (j0 * 4 + jj) * 32);
                #pragma unroll
                for (int q4 = 0; q4 < 8; q4++) {
                    ulonglong2 m = mrow[q4];
                    W2r[2 * q4]     = fma2(m.x, gp, W2r[2 * q4]);
                    W2r[2 * q4 + 1] = fma2(m.y, gp, W2r[2 * q4 + 1]);
                }
            }
        }

        // ---- prefetch genW2 row for next head ----
        if (h < HH - 1) {
            const float4* gsrc =
                reinterpret_cast<const float4*>(genW2 + (size_t)(h + 1) * TT * GH + (size_t)tc * GH);
            #pragma unroll
            for (int i = 0; i < 8; i++) gw[i] = __ldg(gsrc + i);
        }

        // ---- A part: A[b] = feats[b] . attW[h,t,0:64]; feats rows via LDS.128 ----
        unsigned long long A2[4], E2[2];
        #pragma unroll
        for (int d = 0; d < 4; d++) A2[d] = 0ull;
        E2[0] = 0ull; E2[1] = 0ull;
        #pragma unroll
        for (int k0 = 0; k0 < 64; k0 += 4) {
            float4 w4 = *reinterpret_cast<const float4*>(myw + k0);
            float wv[4] = {w4.x, w4.y, w4.z, w4.w};
            #pragma unroll
            for (int kk = 0; kk < 4; kk++) {
                unsigned long long wp = pk2(wv[kk], wv[kk]);
                ulonglong2 fa = fts[(k0 + kk) * 2];
                ulonglong2 fb = fts[(k0 + kk) * 2 + 1];
                A2[0] = fma2(fa.x, wp, A2[0]);
                A2[1] = fma2(fa.y, wp, A2[1]);
                A2[2] = fma2(fb.x, wp, A2[2]);
                A2[3] = fma2(fb.y, wp, A2[3]);
            }
        }
        // ---- E part: E[p] = embeds[p] . attW[h,t,64:96]; LDS.128 rows ----
        #pragma unroll
        for (int k0 = 0; k0 < 32; k0 += 4) {
            float4 w4 = *reinterpret_cast<const float4*>(myw + 64 + k0);
            float wv[4] = {w4.x, w4.y, w4.z, w4.w};
            #pragma unroll
            for (int kk = 0; kk < 4; kk++) {
                unsigned long long wp = pk2(wv[kk], wv[kk]);
                ulonglong2 e = emt[k0 + kk];
                E2[0] = fma2(e.x, wp, E2[0]);
                E2[1] = fma2(e.y, wp, E2[1]);
            }
        }

        // ---- epilogue ----
        float ab  = abv[h];
        float b2v = b2vv[h];
        float A[8], E[4];
        #pragma unroll
        for (int d = 0; d < 4; d++) upk2(A2[d], A[2 * d], A[2 * d + 1]);
        upk2(E2[0], E[0], E[1]);
        upk2(E2[1], E[2], E[3]);
        const float* gr = sh_gate + h * BB;
        #pragma unroll
        for (int q = 0; q < 16; q++) {
            float w0, w1;
            upk2(W2r[q], w0, w1);
            int pb0 = 2 * q;
            int b0 = pb0 & 7;
            int p  = pb0 >> 3;
            float z0 = A[b0]     + E[p] + ab;
            float z1 = A[b0 + 1] + E[p] + ab;
            float i0 = __fdividef(1.f, 1.f + __expf(-z0));
            float i1 = __fdividef(1.f, 1.f + __expf(-z1));
            acc[pb0]     = fmaf((w0 + b2v) * i0, gr[b0],     acc[pb0]);
            acc[pb0 + 1] = fmaf((w1 + b2v) * i1, gr[b0 + 1], acc[pb0 + 1]);
        }

        __syncthreads();   // readers done before next issue overwrites buffer
    }

    if (t < TT) {
        #pragma unroll
        for (int pb = 0; pb < 32; pb++) {
            int p = pb >> 3, b = pb & 7;
            out[(size_t)b * (PP * TT) + (size_t)p * TT + t] = acc[pb];
        }
    }
}

extern "C" void kernel_launch(void* const* d_in, const int* in_sizes, int n_in,
                              void* d_out, int out_size)
{
    const float* x     = (const float*)d_in[0];
    const float* feW1  = (const float*)d_in[1];
    const float* feb1  = (const float*)d_in[2];
    const float* feW2  = (const float*)d_in[3];
    const float* feb2  = (const float*)d_in[4];
    const float* emb   = (const float*)d_in[5];
    const float* genW1 = (const float*)d_in[6];
    const float* genb1 = (const float*)d_in[7];
    const float* genW2 = (const float*)d_in[8];
    const float* genb2 = (const float*)d_in[9];
    const float* attW  = (const float*)d_in[10];
    const float* attb  = (const float*)d_in[11];
    const float* gateW = (const float*)d_in[12];
    const float* gateb = (const float*)d_in[13];
    float* out = (float*)d_out;

    prep1a_kernel<<<128, 256>>>(x, feW1, feb1);
    prep_fuse_kernel<<<8, 256>>>(feW2, feb2, gateW, gateb, emb, genW1, genb1);

    const int SMEM = (2 * AWBUF + 2 * HMBUF + FEAT * BB + EMB * PP + HH * BB) * 4;
    cudaFuncSetAttribute(main_kernel, cudaFuncAttributeMaxDynamicSharedMemorySize, SMEM);
    int grid = (TT + NT - 1) / NT;
    main_kernel<<<grid, TPB, SMEM>>>(genW2, genb2, attW, attb, out);
}

// round 11
// speedup vs baseline: 1.0689x; 1.0689x over previous
#include <cuda_runtime.h>
#include <math.h>
#include <stdint.h>

#define BB 8
#define HH 8
#define PP 4
#define FEAT 64
#define EMB 32
#define HIN 96
#define GH 32
#define TT 101770

#define TPB 128
#define NT 128
#define CH_COLS 48                      // columns per attW chunk
#define CH_STR 52                       // padded smem stride (words)
#define CHBUF (NT * CH_STR)             // 6656 floats per chunk buffer
#define HMBUF (GH * 32)                 // 1024 floats per hmid slice

// ---------- persistent scratch ----------
__device__ float g_h1    [BB * 128];
__device__ float g_feats [BB * FEAT];
__device__ float g_featsT[FEAT * BB];   // [k][b]
__device__ float g_embT  [EMB * PP];    // [k][p]
__device__ float g_hmidT [HH * GH * 32];// [h][j][pb]
__device__ float g_gate  [HH * BB];     // [h][b]

// ---------- packed f32x2 helpers ----------
__device__ __forceinline__ unsigned long long pk2(float lo, float hi) {
    unsigned long long r;
    asm("mov.b64 %0, {%1, %2};" : "=l"(r) : "f"(lo), "f"(hi));
    return r;
}
__device__ __forceinline__ unsigned long long fma2(unsigned long long a,
                                                   unsigned long long b,
                                                   unsigned long long c) {
    unsigned long long d;
    asm("fma.rn.f32x2 %0, %1, %2, %3;" : "=l"(d) : "l"(a), "l"(b), "l"(c));
    return d;
}
__device__ __forceinline__ void upk2(unsigned long long v, float& lo, float& hi) {
    asm("mov.b64 {%0, %1}, %2;" : "=f"(lo), "=f"(hi) : "l"(v));
}

// ---------- cp.async helpers ----------
__device__ __forceinline__ void cp16(uint32_t dst_smem, const void* src) {
    asm volatile("cp.async.cg.shared.global [%0], [%1], 16;" :: "r"(dst_smem), "l"(src));
}
__device__ __forceinline__ void cp_commit() { asm volatile("cp.async.commit_group;"); }
template<int N>
__device__ __forceinline__ void cp_wait() {
    asm volatile("cp.async.wait_group %0;" :: "n"(N));
}

// ---------- prep 1a: layer 1, one warp per output (128 blocks x 256 thr) ----------
__global__ void __launch_bounds__(256, 1)
prep1a_kernel(const float* __restrict__ x,
              const float* __restrict__ feW1, const float* __restrict__ feb1)
{
    int g = blockIdx.x * 8 + (threadIdx.x >> 5);
    int lane = threadIdx.x & 31;
    int b = g >> 7, j = g & 127;
    const float* xr = x + b * 784;
    const float* wr = feW1 + j * 784;
    float s = 0.f;
    #pragma unroll 4
    for (int i = lane; i < 784; i += 32) s = fmaf(xr[i], wr[i], s);
    #pragma unroll
    for (int o = 16; o; o >>= 1) s += __shfl_down_sync(0xFFFFFFFFu, s, o);
    if (lane == 0) g_h1[b * 128 + j] = fmaxf(s + feb1[j], 0.f);
}

// ---------- prep fuse: layer 2 (staged, redundant per block) + gate + hmid + embT ----------
__global__ void __launch_bounds__(256, 1)
prep_fuse_kernel(const float* __restrict__ feW2, const float* __restrict__ feb2,
                 const float* __restrict__ gateW, const float* __restrict__ gateb,
                 const float* __restrict__ embeds,
                 const float* __restrict__ genW1, const float* __restrict__ genb1)
{
    int h = blockIdx.x;
    int tid = threadIdx.x;
    __shared__ float s_h1[BB * 128];
    __shared__ float s_w2[FEAT * 128];
    __shared__ float s_feats[BB * FEAT];
    __shared__ float s_emb[PP * EMB];

    for (int i = tid; i < BB * 128; i += 256) s_h1[i] = g_h1[i];
    for (int i = tid; i < FEAT * 128; i += 256) s_w2[i] = feW2[i];
    for (int i = tid; i < PP * EMB; i += 256) s_emb[i] = embeds[i];
    __syncthreads();

    // layer 2: 512 outputs; warp covers 4 f-rows x 8 b (smem broadcast friendly)
    for (int o = tid; o < BB * FEAT; o += 256) {
        int b = o & 7, f = o >> 3;
        float s = feb2[f];
        const float* hr = s_h1 + b * 128;
        const float* wr = s_w2 + f * 128;
        #pragma unroll 8
        for (int j = 0; j < 128; j++) s = fmaf(hr[j], wr[j], s);
        s_feats[b * FEAT + f] = s;
        if (h == 0) {
            g_feats[b * FEAT + f] = s;
            g_featsT[f * BB + b] = s;
        }
    }
    __syncthreads();

    if (h == 0 && tid < 8) {
        int r = tid;
        float lg[8];
        float mx = -1e30f;
        #pragma unroll
        for (int c = 0; c < 8; c++) {
            float s = gateb[c];
            const float* fr = s_feats + r * FEAT;
            const float* wr = gateW + c * FEAT;
            #pragma unroll 8
            for (int k = 0; k < FEAT; k++) s = fmaf(fr[k], wr[k], s);
            lg[c] = s;
            mx = fmaxf(mx, s);
        }
        float den = 0.f;
        #pragma unroll
        for (int c = 0; c < 8; c++) { lg[c] = __expf(lg[c] - mx); den += lg[c]; }
        float inv = 1.f / den;
        #pragma unroll
        for (int c = 0; c < 8; c++) g_gate[r * 8 + c] = lg[c] * inv;
    }
    if (h == 0) {
        for (int i = tid; i < EMB * PP; i += 256) {
            int k = i >> 2, p = i & 3;
            g_embT[k * 4 + p] = embeds[p * EMB + k];
        }
    }

    // hmid for head h: layout [j][pb]
    for (int idx = tid; idx < GH * 32; idx += 256) {
        int j = idx >> 5;
        int pb = idx & 31;
        int p = pb >> 3, b = pb & 7;
        const float* w = genW1 + (size_t)(h * GH + j) * HIN;
        float s = genb1[h * GH + j];
        const float* fr = s_feats + b * FEAT;
        #pragma unroll 8
        for (int i = 0; i < FEAT; i++) s = fmaf(fr[i], w[i], s);
        const float* er = s_emb + p * EMB;
        #pragma unroll 8
        for (int i = 0; i < EMB; i++) s = fmaf(er[i], w[FEAT + i], s);
        g_hmidT[(h * GH + j) * 32 + pb] = fmaxf(s, 0.f);
    }
}

// ---------- main kernel: 3 blocks/SM, column-chunked cp.async pipeline ----------
__global__ void __launch_bounds__(TPB, 3)
main_kernel(const float* __restrict__ genW2, const float* __restrict__ genb2,
            const float* __restrict__ attW,  const float* __restrict__ attb,
            float* __restrict__ out)
{
    extern __shared__ float sm[];
    float* sh_attw   = sm;                          // 2 * CHBUF (chunk c lives in buf c)
    float* sh_hmid   = sm + 2 * CHBUF;              // 2 * 1024
    float* sh_featsT = sh_hmid + 2 * HMBUF;         // 512
    float* sh_embT   = sh_featsT + FEAT * BB;       // 128
    float* sh_gate   = sh_embT + EMB * PP;          // 64

    int tid = threadIdx.x;
    int t_base = blockIdx.x * NT;
    int t = t_base + tid;
    int tc = (t < TT) ? t : (TT - 1);

    uint32_t smem_u32 = (uint32_t)__cvta_generic_to_shared(sm);

    // stage chunk c of head h (c==0 also stages hmid[h])
    auto issue_stage = [&](int h, int c) {
        uint32_t abase = smem_u32 + (uint32_t)c * (CHBUF * 4);
        const float* src = attW + (size_t)h * TT * HIN + c * CH_COLS;
        #pragma unroll
        for (int i = 0; i < 12; i++) {
            int v = tid + i * TPB;              // [0, 1536)
            int row = v / 12, c4 = v % 12;
            int tr = t_base + row; if (tr >= TT) tr = TT - 1;
            cp16(abase + (uint32_t)(row * CH_STR + c4 * 4) * 4,
                 src + (size_t)tr * HIN + c4 * 4);
        }
        if (c == 0) {
            uint32_t hb = smem_u32 + (uint32_t)(2 * CHBUF + (h & 1) * HMBUF) * 4;
            const float* hsrc = g_hmidT + (size_t)h * HMBUF;
            #pragma unroll
            for (int i = 0; i < 2; i++) {
                int v = tid + i * TPB;
                cp16(hb + (uint32_t)v * 16, hsrc + v * 4);
            }
        }
    };

    issue_stage(0, 0);
    cp_commit();

    // genW2 row prefetch for head 0
    float4 gw[8];
    {
        const float4* gsrc = reinterpret_cast<const float4*>(genW2 + (size_t)tc * GH);
        #pragma unroll
        for (int i = 0; i < 8; i++) gw[i] = __ldg(gsrc + i);
    }

    // small persistent tables
    for (int i = tid; i < FEAT * BB; i += TPB) sh_featsT[i] = g_featsT[i];
    if (tid < EMB * PP) sh_embT[tid] = g_embT[tid];
    if (tid < HH * BB)  sh_gate[tid] = g_gate[tid];

    float acc[32];
    #pragma unroll
    for (int i = 0; i < 32; i++) acc[i] = 0.f;

    const float* myw0 = sh_attw + tid * CH_STR;
    const float* myw1 = sh_attw + CHBUF + tid * CH_STR;

    for (int h = 0; h < HH; h++) {
        // ===== phase 0: chunk (h,0) + hmid[h] =====
        issue_stage(h, 1);
        cp_commit();
        cp_wait<1>();
        __syncthreads();

        const float* hmidb = sh_hmid + (h & 1) * HMBUF;

        // W part: consumes prefetched gw registers
        unsigned long long W2r[16];
        #pragma unroll
        for (int q = 0; q < 16; q++) W2r[q] = 0ull;
        #pragma unroll
        for (int j0 = 0; j0 < 8; j0++) {
            float gv[4] = {gw[j0].x, gw[j0].y, gw[j0].z, gw[j0].w};
            #pragma unroll
            for (int jj = 0; jj < 4; jj++) {
                unsigned long long gp = pk2(gv[jj], gv[jj]);
                const unsigned long long* m2 =
                    reinterpret_cast<const unsigned long long*>(hmidb + (j0 * 4 + jj) * 32);
                #pragma unroll
                for (int q = 0; q < 16; q++) W2r[q] = fma2(m2[q], gp, W2r[q]);
            }
        }

        // prefetch genW2 row for next head
        if (h < HH - 1) {
            const float4* gsrc =
                reinterpret_cast<const float4*>(genW2 + (size_t)(h + 1) * TT * GH + (size_t)tc * GH);
            #pragma unroll
            for (int i = 0; i < 8; i++) gw[i] = __ldg(gsrc + i);
        }

        // A part, k = 0..47
        unsigned long long A2[4], E2[2];
        #pragma unroll
        for (int d = 0; d < 4; d++) A2[d] = 0ull;
        E2[0] = 0ull; E2[1] = 0ull;
        #pragma unroll
        for (int k0 = 0; k0 < 48; k0 += 4) {
            float4 w4 = *reinterpret_cast<const float4*>(myw0 + k0);
            float wv[4] = {w4.x, w4.y, w4.z, w4.w};
            #pragma unroll
            for (int kk = 0; kk < 4; kk++) {
                unsigned long long wp = pk2(wv[kk], wv[kk]);
                const unsigned long long* f2 =
                    reinterpret_cast<const unsigned long long*>(sh_featsT + (k0 + kk) * BB);
                #pragma unroll
                for (int d = 0; d < 4; d++) A2[d] = fma2(f2[d], wp, A2[d]);
            }
        }
        __syncthreads();   // done with buf0 + hmid[h]; next issue may overwrite buf0

        // ===== phase 1: chunk (h,1) =====
        if (h < HH - 1) {
            issue_stage(h + 1, 0);
            cp_commit();
            cp_wait<1>();
        } else {
            cp_wait<0>();
        }
        __syncthreads();

        // per-head biases (latency hidden under A/E below)
        float ab  = __ldg(attb  + (size_t)h * TT + tc);
        float b2v = __ldg(genb2 + (size_t)h * TT + tc);

        // A part, k = 48..63 -> buf1 cols 0..15
        #pragma unroll
        for (int k0 = 0; k0 < 16; k0 += 4) {
            float4 w4 = *reinterpret_cast<const float4*>(myw1 + k0);
            float wv[4] = {w4.x, w4.y, w4.z, w4.w};
            #pragma unroll
            for (int kk = 0; kk < 4; kk++) {
                unsigned long long wp = pk2(wv[kk], wv[kk]);
                const unsigned long long* f2 =
                    reinterpret_cast<const unsigned long long*>(sh_featsT + (48 + k0 + kk) * BB);
                #pragma unroll
                for (int d = 0; d < 4; d++) A2[d] = fma2(f2[d], wp, A2[d]);
            }
        }
        // E part, k = 64..95 -> buf1 cols 16..47
        #pragma unroll
        for (int k0 = 0; k0 < 32; k0 += 4) {
            float4 w4 = *reinterpret_cast<const float4*>(myw1 + 16 + k0);
            float wv[4] = {w4.x, w4.y, w4.z, w4.w};
            #pragma unroll
            for (int kk = 0; kk < 4; kk++) {
                unsigned long long wp = pk2(wv[kk], wv[kk]);
                const unsigned long long* e2 =
                    reinterpret_cast<const unsigned long long*>(sh_embT + (k0 + kk) * PP);
                E2[0] = fma2(e2[0], wp, E2[0]);
                E2[1] = fma2(e2[1], wp, E2[1]);
            }
        }

        // epilogue
        float A[8], E[4];
        #pragma unroll
        for (int d = 0; d < 4; d++) upk2(A2[d], A[2 * d], A[2 * d + 1]);
        upk2(E2[0], E[0], E[1]);
        upk2(E2[1], E[2], E[3]);
        const float* gr = sh_gate + h * BB;
        #pragma unroll
        for (int q = 0; q < 16; q++) {
            float w0, w1;
            upk2(W2r[q], w0, w1);
            int pb0 = 2 * q;
            int b0 = pb0 & 7;
            int p  = pb0 >> 3;
            float z0 = A[b0]     + E[p] + ab;
            float z1 = A[b0 + 1] + E[p] + ab;
            float i0 = __fdividef(1.f, 1.f + __expf(-z0));
            float i1 = __fdividef(1.f, 1.f + __expf(-z1));
            acc[pb0]     = fmaf((w0 + b2v) * i0, gr[b0],     acc[pb0]);
            acc[pb0 + 1] = fmaf((w1 + b2v) * i1, gr[b0 + 1], acc[pb0 + 1]);
        }

        __syncthreads();   // done with buf1 before next head overwrites it
    }

    if (t < TT) {
        #pragma unroll
        for (int pb = 0; pb < 32; pb++) {
            int p = pb >> 3, b = pb & 7;
            out[(size_t)b * (PP * TT) + (size_t)p * TT + t] = acc[pb];
        }
    }
}

extern "C" void kernel_launch(void* const* d_in, const int* in_sizes, int n_in,
                              void* d_out, int out_size)
{
    const float* x     = (const float*)d_in[0];
    const float* feW1  = (const float*)d_in[1];
    const float* feb1  = (const float*)d_in[2];
    const float* feW2  = (const float*)d_in[3];
    const float* feb2  = (const float*)d_in[4];
    const float* emb   = (const float*)d_in[5];
    const float* genW1 = (const float*)d_in[6];
    const float* genb1 = (const float*)d_in[7];
    const float* genW2 = (const float*)d_in[8];
    const float* genb2 = (const float*)d_in[9];
    const float* attW  = (const float*)d_in[10];
    const float* attb  = (const float*)d_in[11];
    const float* gateW = (const float*)d_in[12];
    const float* gateb = (const float*)d_in[13];
    float* out = (float*)d_out;

    prep1a_kernel<<<128, 256>>>(x, feW1, feb1);
    prep_fuse_kernel<<<8, 256>>>(feW2, feb2, gateW, gateb, emb, genW1, genb1);

    const int SMEM = (2 * CHBUF + 2 * HMBUF + FEAT * BB + EMB * PP + HH * BB) * 4;
    cudaFuncSetAttribute(main_kernel, cudaFuncAttributeMaxDynamicSharedMemorySize, SMEM);
    int grid = (TT + NT - 1) / NT;
    main_kernel<<<grid, TPB, SMEM>>>(genW2, genb2, attW, attb, out);
}

// round 12
// speedup vs baseline: 1.2260x; 1.1470x over previous
#include <cuda_runtime.h>
#include <math.h>
#include <stdint.h>

#define BB 8
#define HH 8
#define PP 4
#define FEAT 64
#define EMB 32
#define HIN 96
#define GH 32
#define TT 101770

#define TPB 128
#define NT 256                          // t's per block (2 per thread)
#define CH_STR 36                       // 32 cols + 4 pad (words)
#define CHBUF (NT * CH_STR)             // 9216 floats per chunk buffer
#define HMBUF (GH * 32)                 // 1024 floats per hmid slice

// ---------- persistent scratch ----------
__device__ float g_h1    [BB * 128];
__device__ float g_feats [BB * FEAT];
__device__ float g_featsT[FEAT * BB];   // [k][b]
__device__ float g_embT  [EMB * PP];    // [k][p]
__device__ float g_hmidT [HH * GH * 32];// [h][j][pb]
__device__ float g_gate  [HH * BB];     // [h][b]

// ---------- packed f32x2 helpers ----------
__device__ __forceinline__ unsigned long long pk2(float lo, float hi) {
    unsigned long long r;
    asm("mov.b64 %0, {%1, %2};" : "=l"(r) : "f"(lo), "f"(hi));
    return r;
}
__device__ __forceinline__ unsigned long long fma2(unsigned long long a,
                                                   unsigned long long b,
                                                   unsigned long long c) {
    unsigned long long d;
    asm("fma.rn.f32x2 %0, %1, %2, %3;" : "=l"(d) : "l"(a), "l"(b), "l"(c));
    return d;
}
__device__ __forceinline__ void upk2(unsigned long long v, float& lo, float& hi) {
    asm("mov.b64 {%0, %1}, %2;" : "=f"(lo), "=f"(hi) : "l"(v));
}

// ---------- cp.async helpers ----------
__device__ __forceinline__ void cp16(uint32_t dst_smem, const void* src) {
    asm volatile("cp.async.cg.shared.global [%0], [%1], 16;" :: "r"(dst_smem), "l"(src));
}
__device__ __forceinline__ void cp_commit() { asm volatile("cp.async.commit_group;"); }
template<int N>
__device__ __forceinline__ void cp_wait() {
    asm volatile("cp.async.wait_group %0;" :: "n"(N));
}

// ---------- prep 1a ----------
__global__ void __launch_bounds__(256, 1)
prep1a_kernel(const float* __restrict__ x,
              const float* __restrict__ feW1, const float* __restrict__ feb1)
{
    int g = blockIdx.x * 8 + (threadIdx.x >> 5);
    int lane = threadIdx.x & 31;
    int b = g >> 7, j = g & 127;
    const float* xr = x + b * 784;
    const float* wr = feW1 + j * 784;
    float s = 0.f;
    #pragma unroll 4
    for (int i = lane; i < 784; i += 32) s = fmaf(xr[i], wr[i], s);
    #pragma unroll
    for (int o = 16; o; o >>= 1) s += __shfl_down_sync(0xFFFFFFFFu, s, o);
    if (lane == 0) g_h1[b * 128 + j] = fmaxf(s + feb1[j], 0.f);
}

// ---------- prep fuse ----------
__global__ void __launch_bounds__(256, 1)
prep_fuse_kernel(const float* __restrict__ feW2, const float* __restrict__ feb2,
                 const float* __restrict__ gateW, const float* __restrict__ gateb,
                 const float* __restrict__ embeds,
                 const float* __restrict__ genW1, const float* __restrict__ genb1)
{
    int h = blockIdx.x;
    int tid = threadIdx.x;
    __shared__ float s_h1[BB * 128];
    __shared__ float s_w2[FEAT * 128];
    __shared__ float s_feats[BB * FEAT];
    __shared__ float s_emb[PP * EMB];

    for (int i = tid; i < BB * 128; i += 256) s_h1[i] = g_h1[i];
    for (int i = tid; i < FEAT * 128; i += 256) s_w2[i] = feW2[i];
    for (int i = tid; i < PP * EMB; i += 256) s_emb[i] = embeds[i];
    __syncthreads();

    for (int o = tid; o < BB * FEAT; o += 256) {
        int b = o & 7, f = o >> 3;
        float s = feb2[f];
        const float* hr = s_h1 + b * 128;
        const float* wr = s_w2 + f * 128;
        #pragma unroll 8
        for (int j = 0; j < 128; j++) s = fmaf(hr[j], wr[j], s);
        s_feats[b * FEAT + f] = s;
        if (h == 0) {
            g_feats[b * FEAT + f] = s;
            g_featsT[f * BB + b] = s;
        }
    }
    __syncthreads();

    if (h == 0 && tid < 8) {
        int r = tid;
        float lg[8];
        float mx = -1e30f;
        #pragma unroll
        for (int c = 0; c < 8; c++) {
            float s = gateb[c];
            const float* fr = s_feats + r * FEAT;
            const float* wr = gateW + c * FEAT;
            #pragma unroll 8
            for (int k = 0; k < FEAT; k++) s = fmaf(fr[k], wr[k], s);
            lg[c] = s;
            mx = fmaxf(mx, s);
        }
        float den = 0.f;
        #pragma unroll
        for (int c = 0; c < 8; c++) { lg[c] = __expf(lg[c] - mx); den += lg[c]; }
        float inv = 1.f / den;
        #pragma unroll
        for (int c = 0; c < 8; c++) g_gate[r * 8 + c] = lg[c] * inv;
    }
    if (h == 0) {
        for (int i = tid; i < EMB * PP; i += 256) {
            int k = i >> 2, p = i & 3;
            g_embT[k * 4 + p] = embeds[p * EMB + k];
        }
    }

    for (int idx = tid; idx < GH * 32; idx += 256) {
        int j = idx >> 5;
        int pb = idx & 31;
        int p = pb >> 3, b = pb & 7;
        const float* w = genW1 + (size_t)(h * GH + j) * HIN;
        float s = genb1[h * GH + j];
        const float* fr = s_feats + b * FEAT;
        #pragma unroll 8
        for (int i = 0; i < FEAT; i++) s = fmaf(fr[i], w[i], s);
        const float* er = s_emb + p * EMB;
        #pragma unroll 8
        for (int i = 0; i < EMB; i++) s = fmaf(er[i], w[FEAT + i], s);
        g_hmidT[(h * GH + j) * 32 + pb] = fmaxf(s, 0.f);
    }
}

// ---------- main kernel: 2 t per thread, 3-phase chunked cp.async pipeline ----------
__global__ void __launch_bounds__(TPB, 2)
main_kernel(const float* __restrict__ genW2, const float* __restrict__ genb2,
            const float* __restrict__ attW,  const float* __restrict__ attb,
            float* __restrict__ out)
{
    extern __shared__ float sm[];
    float* sh_attw   = sm;                          // 2 * CHBUF
    float* sh_hmid   = sm + 2 * CHBUF;              // 2 * HMBUF
    float* sh_featsT = sh_hmid + 2 * HMBUF;         // 512
    float* sh_embT   = sh_featsT + FEAT * BB;       // 128
    float* sh_gate   = sh_embT + EMB * PP;          // 64

    int tid = threadIdx.x;
    int t_base = blockIdx.x * NT;
    int t0 = t_base + tid;
    int t1 = t0 + TPB;
    int tc0 = (t0 < TT) ? t0 : (TT - 1);
    int tc1 = (t1 < TT) ? t1 : (TT - 1);

    uint32_t smem_u32 = (uint32_t)__cvta_generic_to_shared(sm);

    // stage chunk c (32 cols) of head h into buf ((h*3+c)&1); c==2 adds hmid[h]
    auto issue_stage = [&](int h, int c) {
        int gp = h * 3 + c;
        uint32_t abase = smem_u32 + (uint32_t)(gp & 1) * (CHBUF * 4);
        const float* src = attW + (size_t)h * TT * HIN + c * 32;
        #pragma unroll
        for (int i = 0; i < 16; i++) {
            int v = tid + i * TPB;              // [0, 2048)
            int row = v >> 3, c4 = v & 7;
            int tr = t_base + row; if (tr >= TT) tr = TT - 1;
            cp16(abase + (uint32_t)(row * CH_STR + c4 * 4) * 4,
                 src + (size_t)tr * HIN + c4 * 4);
        }
        if (c == 2) {
            uint32_t hb = smem_u32 + (uint32_t)(2 * CHBUF + (h & 1) * HMBUF) * 4;
            const float* hsrc = g_hmidT + (size_t)h * HMBUF;
            #pragma unroll
            for (int i = 0; i < 2; i++) {
                int v = tid + i * TPB;
                cp16(hb + (uint32_t)v * 16, hsrc + v * 4);
            }
        }
    };

    issue_stage(0, 0);
    cp_commit();

    // small persistent tables
    for (int i = tid; i < FEAT * BB; i += TPB) sh_featsT[i] = g_featsT[i];
    if (tid < EMB * PP) sh_embT[tid] = g_embT[tid];
    if (tid < HH * BB)  sh_gate[tid] = g_gate[tid];

    float acc0[32], acc1[32];
    #pragma unroll
    for (int i = 0; i < 32; i++) { acc0[i] = 0.f; acc1[i] = 0.f; }

    unsigned long long A2a[4], A2b[4];
    float4 gw0[8], gw1[8];

    for (int h = 0; h < HH; h++) {
        int gp0 = h * 3;

        // ===== phase 0: chunk 0 (A cols 0..31) =====
        issue_stage(h, 1);
        cp_commit();
        cp_wait<1>();
        __syncthreads();
        {
            const float* base = sh_attw + (gp0 & 1) * CHBUF;
            const float* w0p = base + tid * CH_STR;
            const float* w1p = base + (TPB + tid) * CH_STR;
            #pragma unroll
            for (int d = 0; d < 4; d++) { A2a[d] = 0ull; A2b[d] = 0ull; }
            #pragma unroll
            for (int k0 = 0; k0 < 32; k0 += 4) {
                float4 a4 = *reinterpret_cast<const float4*>(w0p + k0);
                float4 b4 = *reinterpret_cast<const float4*>(w1p + k0);
                float av[4] = {a4.x, a4.y, a4.z, a4.w};
                float bv[4] = {b4.x, b4.y, b4.z, b4.w};
                #pragma unroll
                for (int kk = 0; kk < 4; kk++) {
                    unsigned long long wpa = pk2(av[kk], av[kk]);
                    unsigned long long wpb = pk2(bv[kk], bv[kk]);
                    const unsigned long long* f2 =
                        reinterpret_cast<const unsigned long long*>(sh_featsT + (k0 + kk) * BB);
                    #pragma unroll
                    for (int d = 0; d < 4; d++) {
                        unsigned long long fv = f2[d];
                        A2a[d] = fma2(fv, wpa, A2a[d]);
                        A2b[d] = fma2(fv, wpb, A2b[d]);
                    }
                }
            }
        }
        __syncthreads();

        // ===== phase 1: chunk 1 (A cols 32..63) =====
        issue_stage(h, 2);
        cp_commit();
        cp_wait<1>();
        __syncthreads();

        // genW2 rows for this head (consumed in phase 2; latency under A below)
        {
            const float4* g0 = reinterpret_cast<const float4*>(
                genW2 + (size_t)h * TT * GH + (size_t)tc0 * GH);
            const float4* g1 = reinterpret_cast<const float4*>(
                genW2 + (size_t)h * TT * GH + (size_t)tc1 * GH);
            #pragma unroll
            for (int i = 0; i < 8; i++) { gw0[i] = __ldg(g0 + i); gw1[i] = __ldg(g1 + i); }
        }
        {
            const float* base = sh_attw + ((gp0 + 1) & 1) * CHBUF;
            const float* w0p = base + tid * CH_STR;
            const float* w1p = base + (TPB + tid) * CH_STR;
            #pragma unroll
            for (int k0 = 0; k0 < 32; k0 += 4) {
                float4 a4 = *reinterpret_cast<const float4*>(w0p + k0);
                float4 b4 = *reinterpret_cast<const float4*>(w1p + k0);
                float av[4] = {a4.x, a4.y, a4.z, a4.w};
                float bv[4] = {b4.x, b4.y, b4.z, b4.w};
                #pragma unroll
                for (int kk = 0; kk < 4; kk++) {
                    unsigned long long wpa = pk2(av[kk], av[kk]);
                    unsigned long long wpb = pk2(bv[kk], bv[kk]);
                    const unsigned long long* f2 =
                        reinterpret_cast<const unsigned long long*>(sh_featsT + (32 + k0 + kk) * BB);
                    #pragma unroll
                    for (int d = 0; d < 4; d++) {
                        unsigned long long fv = f2[d];
                        A2a[d] = fma2(fv, wpa, A2a[d]);
                        A2b[d] = fma2(fv, wpb, A2b[d]);
                    }
                }
            }
        }
        __syncthreads();

        // ===== phase 2: chunk 2 (E cols 64..95) + hmid + W + epilogue =====
        if (h < HH - 1) {
            issue_stage(h + 1, 0);
            cp_commit();
            cp_wait<1>();
        } else {
            cp_wait<0>();
        }
        __syncthreads();

        float ab0  = __ldg(attb  + (size_t)h * TT + tc0);
        float ab1  = __ldg(attb  + (size_t)h * TT + tc1);
        float b20  = __ldg(genb2 + (size_t)h * TT + tc0);
        float b21  = __ldg(genb2 + (size_t)h * TT + tc1);

        unsigned long long E2a[2], E2b[2];
        E2a[0] = E2a[1] = 0ull; E2b[0] = E2b[1] = 0ull;
        {
            const float* base = sh_attw + ((gp0 + 2) & 1) * CHBUF;
            const float* w0p = base + tid * CH_STR;
            const float* w1p = base + (TPB + tid) * CH_STR;
            #pragma unroll
            for (int k0 = 0; k0 < 32; k0 += 4) {
                float4 a4 = *reinterpret_cast<const float4*>(w0p + k0);
                float4 b4 = *reinterpret_cast<const float4*>(w1p + k0);
                float av[4] = {a4.x, a4.y, a4.z, a4.w};
                float bv[4] = {b4.x, b4.y, b4.z, b4.w};
                #pragma unroll
                for (int kk = 0; kk < 4; kk++) {
                    unsigned long long wpa = pk2(av[kk], av[kk]);
                    unsigned long long wpb = pk2(bv[kk], bv[kk]);
                    const unsigned long long* e2 =
                        reinterpret_cast<const unsigned long long*>(sh_embT + (k0 + kk) * PP);
                    unsigned long long e0 = e2[0], e1 = e2[1];
                    E2a[0] = fma2(e0, wpa, E2a[0]);
                    E2a[1] = fma2(e1, wpa, E2a[1]);
                    E2b[0] = fma2(e0, wpb, E2b[0]);
                    E2b[1] = fma2(e1, wpb, E2b[1]);
                }
            }
        }

        // W part for both t
        unsigned long long W2a[16], W2b[16];
        #pragma unroll
        for (int q = 0; q < 16; q++) { W2a[q] = 0ull; W2b[q] = 0ull; }
        {
            const float* hmidb = sh_hmid + (h & 1) * HMBUF;
            #pragma unroll
            for (int j0 = 0; j0 < 8; j0++) {
                float ga[4] = {gw0[j0].x, gw0[j0].y, gw0[j0].z, gw0[j0].w};
                float gb[4] = {gw1[j0].x, gw1[j0].y, gw1[j0].z, gw1[j0].w};
                #pragma unroll
                for (int jj = 0; jj < 4; jj++) {
                    unsigned long long gpa = pk2(ga[jj], ga[jj]);
                    unsigned long long gpb = pk2(gb[jj], gb[jj]);
                    const unsigned long long* m2 =
                        reinterpret_cast<const unsigned long long*>(hmidb + (j0 * 4 + jj) * 32);
                    #pragma unroll
                    for (int q = 0; q < 16; q++) {
                        unsigned long long m = m2[q];
                        W2a[q] = fma2(m, gpa, W2a[q]);
                        W2b[q] = fma2(m, gpb, W2b[q]);
                    }
                }
            }
        }

        // epilogue for both t
        const float* gr = sh_gate + h * BB;
        {
            float A[8], E[4];
            #pragma unroll
            for (int d = 0; d < 4; d++) upk2(A2a[d], A[2 * d], A[2 * d + 1]);
            upk2(E2a[0], E[0], E[1]);
            upk2(E2a[1], E[2], E[3]);
            #pragma unroll
            for (int q = 0; q < 16; q++) {
                float w0, w1;
                upk2(W2a[q], w0, w1);
                int pb0 = 2 * q;
                int b0 = pb0 & 7;
                int p  = pb0 >> 3;
                float z0 = A[b0]     + E[p] + ab0;
                float z1 = A[b0 + 1] + E[p] + ab0;
                float i0 = __fdividef(1.f, 1.f + __expf(-z0));
                float i1 = __fdividef(1.f, 1.f + __expf(-z1));
                acc0[pb0]     = fmaf((w0 + b20) * i0, gr[b0],     acc0[pb0]);
                acc0[pb0 + 1] = fmaf((w1 + b20) * i1, gr[b0 + 1], acc0[pb0 + 1]);
            }
        }
        {
            float A[8], E[4];
            #pragma unroll
            for (int d = 0; d < 4; d++) upk2(A2b[d], A[2 * d], A[2 * d + 1]);
            upk2(E2b[0], E[0], E[1]);
            upk2(E2b[1], E[2], E[3]);
            #pragma unroll
            for (int q = 0; q < 16; q++) {
                float w0, w1;
                upk2(W2b[q], w0, w1);
                int pb0 = 2 * q;
                int b0 = pb0 & 7;
                int p  = pb0 >> 3;
                float z0 = A[b0]     + E[p] + ab1;
                float z1 = A[b0 + 1] + E[p] + ab1;
                float i0 = __fdividef(1.f, 1.f + __expf(-z0));
                float i1 = __fdividef(1.f, 1.f + __expf(-z1));
                acc1[pb0]     = fmaf((w0 + b21) * i0, gr[b0],     acc1[pb0]);
                acc1[pb0 + 1] = fmaf((w1 + b21) * i1, gr[b0 + 1], acc1[pb0 + 1]);
            }
        }

        __syncthreads();
    }

    if (t0 < TT) {
        #pragma unroll
        for (int pb = 0; pb < 32; pb++) {
            int p = pb >> 3, b = pb & 7;
            out[(size_t)b * (PP * TT) + (size_t)p * TT + t0] = acc0[pb];
        }
    }
    if (t1 < TT) {
        #pragma unroll
        for (int pb = 0; pb < 32; pb++) {
            int p = pb >> 3, b = pb & 7;
            out[(size_t)b * (PP * TT) + (size_t)p * TT + t1] = acc1[pb];
        }
    }
}

extern "C" void kernel_launch(void* const* d_in, const int* in_sizes, int n_in,
                              void* d_out, int out_size)
{
    const float* x     = (const float*)d_in[0];
    const float* feW1  = (const float*)d_in[1];
    const float* feb1  = (const float*)d_in[2];
    const float* feW2  = (const float*)d_in[3];
    const float* feb2  = (const float*)d_in[4];
    const float* emb   = (const float*)d_in[5];
    const float* genW1 = (const float*)d_in[6];
    const float* genb1 = (const float*)d_in[7];
    const float* genW2 = (const float*)d_in[8];
    const float* genb2 = (const float*)d_in[9];
    const float* attW  = (const float*)d_in[10];
    const float* attb  = (const float*)d_in[11];
    const float* gateW = (const float*)d_in[12];
    const float* gateb = (const float*)d_in[13];
    float* out = (float*)d_out;

    prep1a_kernel<<<128, 256>>>(x, feW1, feb1);
    prep_fuse_kernel<<<8, 256>>>(feW2, feb2, gateW, gateb, emb, genW1, genb1);

    const int SMEM = (2 * CHBUF + 2 * HMBUF + FEAT * BB + EMB * PP + HH * BB) * 4;
    cudaFuncSetAttribute(main_kernel, cudaFuncAttributeMaxDynamicSharedMemorySize, SMEM);
    int grid = (TT + NT - 1) / NT;
    main_kernel<<<grid, TPB, SMEM>>>(genW2, genb2, attW, attb, out);
}

// round 14
// speedup vs baseline: 1.3321x; 1.0866x over previous
#include <cuda_runtime.h>
#include <math.h>
#include <stdint.h>

#define BB 8
#define HH 8
#define PP 4
#define FEAT 64
#define EMB 32
#define HIN 96
#define GH 32
#define TT 101770

#define TPB 128
#define NT 128
#define STR 36                       // chunk/genW2/hmid row stride (words): 36 mod 32 = 4
#define HSTR 100                     // hin row stride: 100 mod 32 = 4
#define CHBUF (NT * STR)             // 4608 floats per chunk buffer

// smem offsets (floats)
#define SM_CH    0                   // 2 * 4608
#define SM_HIN   (2 * CHBUF)         // 32*100 = 3200
#define SM_HMID  (SM_HIN + 32 * HSTR)        // 32*36 = 1152
#define SM_ATTB  (SM_HMID + 32 * STR)        // 2*128
#define SM_B2    (SM_ATTB + 256)             // 2*128
#define SM_GATE  (SM_B2 + 256)               // 64
#define SM_TOT_F (SM_GATE + 64)

// ---------- persistent scratch ----------
__device__ float g_h1[BB * 128];
__device__ __align__(16) float g_feats[BB * FEAT];       // [b][k]
__device__ __align__(16) float g_hmidPB[HH * 32 * GH];   // [h][pb][j]
__device__ float g_gate[HH * BB];                        // [h][b]

// ---------- helpers ----------
__device__ __forceinline__ void cp16(uint32_t dst, const void* src) {
    asm volatile("cp.async.cg.shared.global [%0], [%1], 16;" :: "r"(dst), "l"(src));
}
__device__ __forceinline__ void cp4(uint32_t dst, const void* src) {
    asm volatile("cp.async.ca.shared.global [%0], [%1], 4;" :: "r"(dst), "l"(src));
}
__device__ __forceinline__ void cp_commit() { asm volatile("cp.async.commit_group;"); }
template<int N>
__device__ __forceinline__ void cp_wait() {
    asm volatile("cp.async.wait_group %0;" :: "n"(N));
}
__device__ __forceinline__ uint32_t f2tf(float f) {
    uint32_t r;
    asm("cvt.rna.tf32.f32 %0, %1;" : "=r"(r) : "f"(f));
    return r;
}
__device__ __forceinline__ void mma8(float* d, uint32_t a0, uint32_t a1,
                                     uint32_t a2, uint32_t a3,
                                     uint32_t b0, uint32_t b1) {
    asm volatile(
        "mma.sync.aligned.m16n8k8.row.col.f32.tf32.tf32.f32 "
        "{%0,%1,%2,%3}, {%4,%5,%6,%7}, {%8,%9}, {%0,%1,%2,%3};"
        : "+f"(d[0]), "+f"(d[1]), "+f"(d[2]), "+f"(d[3])
        : "r"(a0), "r"(a1), "r"(a2), "r"(a3), "r"(b0), "r"(b1));
}

// ---------- prep 1a: layer 1 ----------
__global__ void __launch_bounds__(256, 1)
prep1a_kernel(const float* __restrict__ x,
              const float* __restrict__ feW1, const float* __restrict__ feb1)
{
    int g = blockIdx.x * 8 + (threadIdx.x >> 5);
    int lane = threadIdx.x & 31;
    int b = g >> 7, j = g & 127;
    const float* xr = x + b * 784;
    const float* wr = feW1 + j * 784;
    float s = 0.f;
    #pragma unroll 4
    for (int i = lane; i < 784; i += 32) s = fmaf(xr[i], wr[i], s);
    #pragma unroll
    for (int o = 16; o; o >>= 1) s += __shfl_down_sync(0xFFFFFFFFu, s, o);
    if (lane == 0) g_h1[b * 128 + j] = fmaxf(s + feb1[j], 0.f);
}

// ---------- prep fuse: layer2 + gate + hmid(pb-major) ----------
__global__ void __launch_bounds__(256, 1)
prep_fuse_kernel(const float* __restrict__ feW2, const float* __restrict__ feb2,
                 const float* __restrict__ gateW, const float* __restrict__ gateb,
                 const float* __restrict__ embeds,
                 const float* __restrict__ genW1, const float* __restrict__ genb1)
{
    int h = blockIdx.x;
    int tid = threadIdx.x;
    __shared__ float s_h1[BB * 128];
    __shared__ float s_w2[FEAT * 128];
    __shared__ float s_feats[BB * FEAT];
    __shared__ float s_emb[PP * EMB];

    for (int i = tid; i < BB * 128; i += 256) s_h1[i] = g_h1[i];
    for (int i = tid; i < FEAT * 128; i += 256) s_w2[i] = feW2[i];
    for (int i = tid; i < PP * EMB; i += 256) s_emb[i] = embeds[i];
    __syncthreads();

    for (int o = tid; o < BB * FEAT; o += 256) {
        int b = o & 7, f = o >> 3;
        float s = feb2[f];
        const float* hr = s_h1 + b * 128;
        const float* wr = s_w2 + f * 128;
        #pragma unroll 8
        for (int j = 0; j < 128; j++) s = fmaf(hr[j], wr[j], s);
        s_feats[b * FEAT + f] = s;
        if (h == 0) g_feats[b * FEAT + f] = s;
    }
    __syncthreads();

    if (h == 0 && tid < 8) {
        int r = tid;
        float lg[8];
        float mx = -1e30f;
        #pragma unroll
        for (int c = 0; c < 8; c++) {
            float s = gateb[c];
            const float* fr = s_feats + r * FEAT;
            const float* wr = gateW + c * FEAT;
            #pragma unroll 8
            for (int k = 0; k < FEAT; k++) s = fmaf(fr[k], wr[k], s);
            lg[c] = s;
            mx = fmaxf(mx, s);
        }
        float den = 0.f;
        #pragma unroll
        for (int c = 0; c < 8; c++) { lg[c] = __expf(lg[c] - mx); den += lg[c]; }
        float inv = 1.f / den;
        #pragma unroll
        for (int c = 0; c < 8; c++) g_gate[r * 8 + c] = lg[c] * inv;
    }

    // hmid for head h, pb-major: g_hmidPB[h][pb][j]
    for (int idx = tid; idx < 32 * GH; idx += 256) {
        int pb = idx >> 5;
        int j = idx & 31;
        int p = pb >> 3, b = pb & 7;
        const float* w = genW1 + (size_t)(h * GH + j) * HIN;
        float s = genb1[h * GH + j];
        const float* fr = s_feats + b * FEAT;
        #pragma unroll 8
        for (int i = 0; i < FEAT; i++) s = fmaf(fr[i], w[i], s);
        const float* er = s_emb + p * EMB;
        #pragma unroll 8
        for (int i = 0; i < EMB; i++) s = fmaf(er[i], w[FEAT + i], s);
        g_hmidPB[h * 1024 + pb * 32 + j] = fmaxf(s, 0.f);
    }
}

// ---------- main kernel: tf32 mma.sync, 4-phase/head cp.async pipeline ----------
__global__ void __launch_bounds__(TPB, 3)
main_kernel(const float* __restrict__ genW2, const float* __restrict__ genb2,
            const float* __restrict__ attW,  const float* __restrict__ attb,
            const float* __restrict__ embeds,
            float* __restrict__ out)
{
    extern __shared__ float sm[];
    float* sm_hin  = sm + SM_HIN;
    float* sm_hmid = sm + SM_HMID;
    float* sm_attb = sm + SM_ATTB;
    float* sm_b2   = sm + SM_B2;
    float* sm_gate = sm + SM_GATE;

    int tid = threadIdx.x;
    int w   = tid >> 5;
    int lane = tid & 31;
    int g   = lane >> 2;      // groupID 0..7
    int tig = lane & 3;       // thread-in-group 0..3
    int t_base = blockIdx.x * NT;

    uint32_t smem_u32 = (uint32_t)__cvta_generic_to_shared(sm);

    // stage phase ph = h*4+c into buffer ph&1
    auto issue_phase = [&](int ph) {
        int h = ph >> 2, c = ph & 3;
        uint32_t chb = smem_u32 + (uint32_t)((ph & 1) * CHBUF) * 4;
        if (c < 3) {
            const float* src = attW + (size_t)h * TT * HIN + c * 32;
            #pragma unroll
            for (int i = 0; i < 8; i++) {
                int v = tid + i * TPB;          // [0, 1024)
                int row = v >> 3, cc = v & 7;
                int tr = t_base + row; if (tr >= TT) tr = TT - 1;
                cp16(chb + (uint32_t)(row * STR + cc * 4) * 4,
                     src + (size_t)tr * HIN + cc * 4);
            }
            if (c == 0) {
                int tr = t_base + tid; if (tr >= TT) tr = TT - 1;
                uint32_t slot = (uint32_t)((h & 1) * 128 + tid) * 4;
                cp4(smem_u32 + (uint32_t)SM_ATTB * 4 + slot, attb  + (size_t)h * TT + tr);
                cp4(smem_u32 + (uint32_t)SM_B2   * 4 + slot, genb2 + (size_t)h * TT + tr);
            }
        } else {
            const float* src = genW2 + (size_t)h * TT * GH;
            #pragma unroll
            for (int i = 0; i < 8; i++) {
                int v = tid + i * TPB;
                int row = v >> 3, cc = v & 7;
                int tr = t_base + row; if (tr >= TT) tr = TT - 1;
                cp16(chb + (uint32_t)(row * STR + cc * 4) * 4,
                     src + (size_t)tr * GH + cc * 4);
            }
            const float* hs = g_hmidPB + (size_t)h * 1024;
            #pragma unroll
            for (int i = 0; i < 2; i++) {
                int v = tid + i * TPB;          // [0, 256)
                int pb = v >> 3, cc = v & 7;
                cp16(smem_u32 + (uint32_t)(SM_HMID + pb * STR + cc * 4) * 4,
                     hs + pb * 32 + cc * 4);
            }
        }
    };

    issue_phase(0);
    cp_commit();

    // stage hin [pb][k] (stride 100) + gate
    for (int v = tid; v < 32 * 24; v += TPB) {
        int pb = v / 24, c4 = v % 24;
        int p = pb >> 3, b = pb & 7;
        float4 val = (c4 < 16)
            ? *reinterpret_cast<const float4*>(g_feats + b * FEAT + c4 * 4)
            : *reinterpret_cast<const float4*>(embeds + p * EMB + (c4 - 16) * 4);
        *reinterpret_cast<float4*>(sm_hin + pb * HSTR + c4 * 4) = val;
    }
    if (tid < HH * BB) sm_gate[tid] = g_gate[tid];

    float zacc[32], wacc[32], acc[32];
    #pragma unroll
    for (int i = 0; i < 32; i++) acc[i] = 0.f;

    for (int ph = 0; ph < 32; ph++) {
        if (ph < 31) { issue_phase(ph + 1); cp_commit(); cp_wait<1>(); }
        else         { cp_wait<0>(); }
        __syncthreads();

        int h = ph >> 2, c = ph & 3;
        const float* chb = sm + (ph & 1) * CHBUF;

        if (c < 3) {
            if (c == 0) {
                #pragma unroll
                for (int i = 0; i < 32; i++) zacc[i] = 0.f;
            }
            #pragma unroll
            for (int ks = 0; ks < 4; ks++) {
                int col = ks * 8 + tig;
                uint32_t B0[4], B1[4];
                #pragma unroll
                for (int nt = 0; nt < 4; nt++) {
                    const float* hp = sm_hin + (nt * 8 + g) * HSTR + c * 32 + col;
                    B0[nt] = f2tf(hp[0]);
                    B1[nt] = f2tf(hp[4]);
                }
                uint32_t A[2][4];
                #pragma unroll
                for (int mt = 0; mt < 2; mt++) {
                    const float* ap  = chb + (w * 32 + mt * 16 + g) * STR + col;
                    const float* ap8 = ap + 8 * STR;
                    A[mt][0] = f2tf(ap[0]);
                    A[mt][1] = f2tf(ap8[0]);
                    A[mt][2] = f2tf(ap[4]);
                    A[mt][3] = f2tf(ap8[4]);
                }
                #pragma unroll
                for (int mt = 0; mt < 2; mt++)
                    #pragma unroll
                    for (int nt = 0; nt < 4; nt++)
                        mma8(&zacc[(mt * 4 + nt) * 4],
                             A[mt][0], A[mt][1], A[mt][2], A[mt][3],
                             B0[nt], B1[nt]);
            }
        } else {
            #pragma unroll
            for (int i = 0; i < 32; i++) wacc[i] = 0.f;
            #pragma unroll
            for (int ks = 0; ks < 4; ks++) {
                int col = ks * 8 + tig;
                uint32_t B0[4], B1[4];
                #pragma unroll
                for (int nt = 0; nt < 4; nt++) {
                    const float* hp = sm_hmid + (nt * 8 + g) * STR + col;
                    B0[nt] = f2tf(hp[0]);
                    B1[nt] = f2tf(hp[4]);
                }
                uint32_t A[2][4];
                #pragma unroll
                for (int mt = 0; mt < 2; mt++) {
                    const float* ap  = chb + (w * 32 + mt * 16 + g) * STR + col;
                    const float* ap8 = ap + 8 * STR;
                    A[mt][0] = f2tf(ap[0]);
                    A[mt][1] = f2tf(ap8[0]);
                    A[mt][2] = f2tf(ap[4]);
                    A[mt][3] = f2tf(ap8[4]);
                }
                #pragma unroll
                for (int mt = 0; mt < 2; mt++)
                    #pragma unroll
                    for (int nt = 0; nt < 4; nt++)
                        mma8(&wacc[(mt * 4 + nt) * 4],
                             A[mt][0], A[mt][1], A[mt][2], A[mt][3],
                             B0[nt], B1[nt]);
            }

            // ---- epilogue for head h ----
            int par = h & 1;
            float ab[2][2], bb[2][2];
            #pragma unroll
            for (int mt = 0; mt < 2; mt++)
                #pragma unroll
                for (int rr = 0; rr < 2; rr++) {
                    int tl = w * 32 + mt * 16 + rr * 8 + g;
                    ab[mt][rr] = sm_attb[par * 128 + tl];
                    bb[mt][rr] = sm_b2[par * 128 + tl];
                }
            float gr0 = sm_gate[h * BB + 2 * tig];
            float gr1 = sm_gate[h * BB + 2 * tig + 1];
            #pragma unroll
            for (int mt = 0; mt < 2; mt++)
                #pragma unroll
                for (int nt = 0; nt < 4; nt++)
                    #pragma unroll
                    for (int r = 0; r < 4; r++) {
                        int idx = (mt * 4 + nt) * 4 + r;
                        int rr = r >> 1;
                        float z = zacc[idx] + ab[mt][rr];
                        float wv = wacc[idx] + bb[mt][rr];
                        float imp = __fdividef(1.f, 1.f + __expf(-z));
                        float gv = (r & 1) ? gr1 : gr0;
                        acc[idx] = fmaf(wv * imp, gv, acc[idx]);
                    }
        }
        __syncthreads();
    }

    // ---- store: acc fragment layout -> out[b][p][t] ----
    #pragma unroll
    for (int mt = 0; mt < 2; mt++)
        #pragma unroll
        for (int r = 0; r < 4; r++) {
            int tl = w * 32 + mt * 16 + (r >> 1) * 8 + g;
            int t = t_base + tl;
            if (t < TT) {
                int bo = 2 * tig + (r & 1);
                #pragma unroll
                for (int nt = 0; nt < 4; nt++)
                    out[(size_t)bo * (PP * TT) + (size_t)nt * TT + t] =
                        acc[(mt * 4 + nt) * 4 + r];
            }
        }
}

extern "C" void kernel_launch(void* const* d_in, const int* in_sizes, int n_in,
                              void* d_out, int out_size)
{
    const float* x     = (const float*)d_in[0];
    const float* feW1  = (const float*)d_in[1];
    const float* feb1  = (const float*)d_in[2];
    const float* feW2  = (const float*)d_in[3];
    const float* feb2  = (const float*)d_in[4];
    const float* emb   = (const float*)d_in[5];
    const float* genW1 = (const float*)d_in[6];
    const float* genb1 = (const float*)d_in[7];
    const float* genW2 = (const float*)d_in[8];
    const float* genb2 = (const float*)d_in[9];
    const float* attW  = (const float*)d_in[10];
    const float* attb  = (const float*)d_in[11];
    const float* gateW = (const float*)d_in[12];
    const float* gateb = (const float*)d_in[13];
    float* out = (float*)d_out;

    prep1a_kernel<<<128, 256>>>(x, feW1, feb1);
    prep_fuse_kernel<<<8, 256>>>(feW2, feb2, gateW, gateb, emb, genW1, genb1);

    const int SMEM = SM_TOT_F * 4;
    cudaFuncSetAttribute(main_kernel, cudaFuncAttributeMaxDynamicSharedMemorySize, SMEM);
    int grid = (TT + NT - 1) / NT;
    main_kernel<<<grid, TPB, SMEM>>>(genW2, genb2, attW, attb, emb, out);
}